// round 1
// baseline (speedup 1.0000x reference)
#include <cuda_runtime.h>

// Problem shapes (compile-time constants)
#define BATCH 8
#define NC    28
#define HH    256
#define WCC   310
#define WPP   256

static constexpr int HWC = HH * WCC;                 // 79360
static constexpr int HWP = HH * WPP;                 // 65536
static constexpr int NPIX_C = BATCH * HWC;           // 634880  (= 2480 * 256 exactly)
static constexpr int NPIX_P = BATCH * HWP;           // 524288
static constexpr int XC_ELEMS = BATCH * NC * HWC;    // 17,776,640

__global__ void __launch_bounds__(256)
dp_fused_kernel(const float* __restrict__ z,
                const float* __restrict__ yc,
                const float* __restrict__ phi_c,
                const float* __restrict__ yp,
                const float* __restrict__ phi_p,
                const float* __restrict__ xc_k_1,
                const float* __restrict__ xp_k_1,
                const float* __restrict__ mu,
                const float* __restrict__ mu_c,
                const float* __restrict__ mu_p,
                float* __restrict__ out)
{
    const int idx = blockIdx.x * blockDim.x + threadIdx.x;
    const float mu_ = mu[0];

    if (idx < NPIX_C) {
        // ---------------- xc update (coded domain, W=310) ----------------
        const float muc = mu_c[0];
        const int b   = idx / HWC;
        const int rem = idx - b * HWC;           // h*WC + w
        const int base = b * (NC * HWC) + rem;   // offset of channel 0

        float zr[NC], pr[NC], xr[NC];
        float s = 0.f, az = 0.f, ax = 0.f;
        #pragma unroll
        for (int c = 0; c < NC; ++c) {
            const int o = base + c * HWC;
            const float zv = z[o];
            const float pv = phi_c[o];
            const float xv = xp_k_1[o];
            zr[c] = zv; pr[c] = pv; xr[c] = xv;
            s  = fmaf(pv, pv, s);
            az = fmaf(zv, pv, az);
            ax = fmaf(xv, pv, ax);
        }
        if (s == 0.f) s = 1.f;
        const float denom = mu_ + muc + s;
        const float y   = yc[idx];
        const float inv = 1.f / (mu_ + muc);
        const float wc_ = muc * inv;
        const float wz  = mu_ * inv;
        const float t   = (wc_ * (y - az) + wz * (y - ax)) / denom;

        #pragma unroll
        for (int c = 0; c < NC; ++c) {
            out[base + c * HWC] = fmaf(wc_, zr[c], fmaf(wz, xr[c], t * pr[c]));
        }
    } else {
        // ---------------- xp update (PAN domain, W=256) ----------------
        const int j = idx - NPIX_C;
        if (j >= NPIX_P) return;
        const float mup = mu_p[0];
        const int b   = j / HWP;
        const int rem = j - b * HWP;             // h*WP + w
        const int h   = rem >> 8;                // WP = 256
        const int w   = rem & 255;
        const int basep = b * (NC * HWP) + rem;                  // phi_p / xc_k_1 / out
        const int basec = b * (NC * HWC) + h * WCC + w;          // z (shifted-back read)

        float zr[NC], pr[NC], xr[NC];
        float s = 0.f, az = 0.f, ax = 0.f;
        #pragma unroll
        for (int c = 0; c < NC; ++c) {
            // shift_back: z[b,c,h,(w+2c)%310]; since w<=255, c<=27 -> w+2c<=309, no wrap
            const float zv = z[basec + c * HWC + 2 * c];
            const int  o  = basep + c * HWP;
            const float pv = phi_p[o];
            const float xv = xc_k_1[o];
            zr[c] = zv; pr[c] = pv; xr[c] = xv;
            s  = fmaf(pv, pv, s);
            az = fmaf(zv, pv, az);
            ax = fmaf(xv, pv, ax);
        }
        if (s == 0.f) s = 1.f;
        const float denom = mu_ + mup + s;
        const float y   = yp[j];
        const float inv = 1.f / (mu_ + mup);
        const float wp_ = mup * inv;
        const float wz  = mu_ * inv;
        const float t   = (wp_ * (y - az) + wz * (y - ax)) / denom;

        float* __restrict__ outp = out + XC_ELEMS;
        #pragma unroll
        for (int c = 0; c < NC; ++c) {
            outp[basep + c * HWP] = fmaf(wp_, zr[c], fmaf(wz, xr[c], t * pr[c]));
        }
    }
}

extern "C" void kernel_launch(void* const* d_in, const int* in_sizes, int n_in,
                              void* d_out, int out_size)
{
    const float* z      = (const float*)d_in[0];
    const float* yc     = (const float*)d_in[1];
    const float* phi_c  = (const float*)d_in[2];
    const float* yp     = (const float*)d_in[3];
    const float* phi_p  = (const float*)d_in[4];
    const float* xc_k_1 = (const float*)d_in[5];
    const float* xp_k_1 = (const float*)d_in[6];
    const float* mu     = (const float*)d_in[7];
    const float* mu_c   = (const float*)d_in[8];
    const float* mu_p   = (const float*)d_in[9];
    float* out = (float*)d_out;

    const int total = NPIX_C + NPIX_P;           // 1,159,168
    const int threads = 256;
    const int blocks = (total + threads - 1) / threads;  // 4528; xc/xp split on block 2480
    dp_fused_kernel<<<blocks, threads>>>(z, yc, phi_c, yp, phi_p,
                                         xc_k_1, xp_k_1, mu, mu_c, mu_p, out);
}

// round 2
// speedup vs baseline: 1.1096x; 1.1096x over previous
#include <cuda_runtime.h>

// Problem shapes (compile-time constants)
#define BATCH 8
#define NC    28
#define HH    256
#define WCC   310
#define WPP   256

static constexpr int HWC = HH * WCC;                 // 79360
static constexpr int HWP = HH * WPP;                 // 65536
static constexpr int NPIX_C = BATCH * HWC;           // 634880  (= 2480 * 256)
static constexpr int NPIX_P = BATCH * HWP;           // 524288  (= 2048 * 256)
static constexpr int XC_ELEMS = BATCH * NC * HWC;    // 17,776,640

// Block-schedule interleave: 2480 xc blocks + 2048 xp blocks
//   = 16 groups x (155 xc + 128 xp) blocks.
// Each group covers HALF of one batch image in BOTH domains
// (155*256 = 39680 = HWC/2 xc pixels; 128*256 = 32768 = HWP/2 xp pixels),
// so the xp path's shifted z reads hit the z lines the xc path just
// pulled into L2 (4.4 MB/group << 126 MB L2).
static constexpr int XC_BLK_PER_GRP = 155;
static constexpr int GRP_BLKS = 283;                 // 155 + 128

__global__ void __launch_bounds__(256)
dp_fused_kernel(const float* __restrict__ z,
                const float* __restrict__ yc,
                const float* __restrict__ phi_c,
                const float* __restrict__ yp,
                const float* __restrict__ phi_p,
                const float* __restrict__ xc_k_1,
                const float* __restrict__ xp_k_1,
                const float* __restrict__ mu,
                const float* __restrict__ mu_c,
                const float* __restrict__ mu_p,
                float* __restrict__ out)
{
    const int g = blockIdx.x / GRP_BLKS;
    const int j = blockIdx.x - g * GRP_BLKS;
    const float mu_ = mu[0];

    if (j < XC_BLK_PER_GRP) {
        // ---------------- xc update (coded domain, W=310) ----------------
        const int idx = (g * XC_BLK_PER_GRP + j) * 256 + threadIdx.x;  // < NPIX_C
        const float muc = mu_c[0];
        const int b   = idx / HWC;
        const int rem = idx - b * HWC;           // h*WC + w
        const int base = b * (NC * HWC) + rem;   // offset of channel 0

        float zr[NC], pr[NC], xr[NC];
        float s = 0.f, az = 0.f, ax = 0.f;
        #pragma unroll
        for (int c = 0; c < NC; ++c) {
            const int o = base + c * HWC;
            const float zv = z[o];
            const float pv = phi_c[o];
            const float xv = xp_k_1[o];
            zr[c] = zv; pr[c] = pv; xr[c] = xv;
            s  = fmaf(pv, pv, s);
            az = fmaf(zv, pv, az);
            ax = fmaf(xv, pv, ax);
        }
        if (s == 0.f) s = 1.f;
        const float denom = mu_ + muc + s;
        const float y   = yc[idx];
        const float inv = 1.f / (mu_ + muc);
        const float wc_ = muc * inv;
        const float wz  = mu_ * inv;
        const float t   = (wc_ * (y - az) + wz * (y - ax)) / denom;

        #pragma unroll
        for (int c = 0; c < NC; ++c) {
            out[base + c * HWC] = fmaf(wc_, zr[c], fmaf(wz, xr[c], t * pr[c]));
        }
    } else {
        // ---------------- xp update (PAN domain, W=256) ----------------
        const int jb = (g * (GRP_BLKS - XC_BLK_PER_GRP) + (j - XC_BLK_PER_GRP));
        const int jj = jb * 256 + threadIdx.x;   // < NPIX_P
        const float mup = mu_p[0];
        const int b   = jj / HWP;
        const int rem = jj - b * HWP;            // h*WP + w
        const int h   = rem >> 8;                // WP = 256
        const int w   = rem & 255;
        const int basep = b * (NC * HWP) + rem;                  // phi_p / xc_k_1 / out
        const int basec = b * (NC * HWC) + h * WCC + w;          // z (shifted-back read)

        float zr[NC], pr[NC], xr[NC];
        float s = 0.f, az = 0.f, ax = 0.f;
        #pragma unroll
        for (int c = 0; c < NC; ++c) {
            // shift_back: z[b,c,h,(w+2c)%310]; w<=255, c<=27 -> w+2c<=309, no wrap
            const float zv = z[basec + c * HWC + 2 * c];
            const int  o  = basep + c * HWP;
            const float pv = phi_p[o];
            const float xv = xc_k_1[o];
            zr[c] = zv; pr[c] = pv; xr[c] = xv;
            s  = fmaf(pv, pv, s);
            az = fmaf(zv, pv, az);
            ax = fmaf(xv, pv, ax);
        }
        if (s == 0.f) s = 1.f;
        const float denom = mu_ + mup + s;
        const float y   = yp[jj];
        const float inv = 1.f / (mu_ + mup);
        const float wp_ = mup * inv;
        const float wz  = mu_ * inv;
        const float t   = (wp_ * (y - az) + wz * (y - ax)) / denom;

        float* __restrict__ outp = out + XC_ELEMS;
        #pragma unroll
        for (int c = 0; c < NC; ++c) {
            outp[basep + c * HWP] = fmaf(wp_, zr[c], fmaf(wz, xr[c], t * pr[c]));
        }
    }
}

extern "C" void kernel_launch(void* const* d_in, const int* in_sizes, int n_in,
                              void* d_out, int out_size)
{
    const float* z      = (const float*)d_in[0];
    const float* yc     = (const float*)d_in[1];
    const float* phi_c  = (const float*)d_in[2];
    const float* yp     = (const float*)d_in[3];
    const float* phi_p  = (const float*)d_in[4];
    const float* xc_k_1 = (const float*)d_in[5];
    const float* xp_k_1 = (const float*)d_in[6];
    const float* mu     = (const float*)d_in[7];
    const float* mu_c   = (const float*)d_in[8];
    const float* mu_p   = (const float*)d_in[9];
    float* out = (float*)d_out;

    const int blocks = (NPIX_C + NPIX_P) / 256;   // 4528 = 16 * 283
    dp_fused_kernel<<<blocks, 256>>>(z, yc, phi_c, yp, phi_p,
                                     xc_k_1, xp_k_1, mu, mu_c, mu_p, out);
}